// round 11
// baseline (speedup 1.0000x reference)
#include <cuda_runtime.h>
#include <cuda_bf16.h>
#include <cstdint>

// ---------------------------------------------------------------------------
// Problem constants
// ---------------------------------------------------------------------------
constexpr int Bc = 4;
constexpr int Ss = 2048;
constexpr int Dd = 1024;
constexpr int Hh = 16;
constexpr int HD = 64;
constexpr int Mtot = Bc * Ss;          // 8192
constexpr int Nqkv = 3 * Dd;           // 3072

// ---------------------------------------------------------------------------
// Scratch (device globals — referenced ONLY from device code)
// ---------------------------------------------------------------------------
__device__ __nv_bfloat16 g_qh[(size_t)Bc * Hh * Ss * HD];  // [B,H,S,HD] (pre-scaled 1/8)
__device__ __nv_bfloat16 g_ql[(size_t)Bc * Hh * Ss * HD];
__device__ __nv_bfloat16 g_kh[(size_t)Bc * Hh * Ss * HD];
__device__ __nv_bfloat16 g_kl[(size_t)Bc * Hh * Ss * HD];
__device__ __nv_bfloat16 g_vh[(size_t)Bc * Hh * Ss * HD];
__device__ __nv_bfloat16 g_vl[(size_t)Bc * Hh * Ss * HD];

__device__ __nv_bfloat16 g_xh[(size_t)Mtot * Dd];
__device__ __nv_bfloat16 g_xl[(size_t)Mtot * Dd];
__device__ __nv_bfloat16 g_oh[(size_t)Mtot * Dd];          // attention out hi/lo
__device__ __nv_bfloat16 g_ol[(size_t)Mtot * Dd];
__device__ __nv_bfloat16 g_wth[(size_t)Nqkv * Dd];         // [N=3072][K=1024] (W^T)
__device__ __nv_bfloat16 g_wtl[(size_t)Nqkv * Dd];
__device__ __nv_bfloat16 g_wph[(size_t)Dd * Dd];           // [N=1024][K=1024] (Wp^T)
__device__ __nv_bfloat16 g_wpl[(size_t)Dd * Dd];
__device__ float g_bias[Nqkv];

// ---------------------------------------------------------------------------
// PTX helpers (baseline ISA only — assembles at .target sm_100)
// ---------------------------------------------------------------------------
__device__ __forceinline__ uint32_t s2u(const void* p) {
    uint32_t a;
    asm("{ .reg .u64 t; cvta.to.shared.u64 t, %1; cvt.u32.u64 %0, t; }"
        : "=r"(a) : "l"(p));
    return a;
}
__device__ __forceinline__ void cpasync16(uint32_t dst, const void* src) {
    asm volatile("cp.async.cg.shared.global [%0], [%1], 16;"
                 :: "r"(dst), "l"(src) : "memory");
}
__device__ __forceinline__ void cpcommit() {
    asm volatile("cp.async.commit_group;" ::: "memory");
}
template<int N> __device__ __forceinline__ void cpwait() {
    asm volatile("cp.async.wait_group %0;" :: "n"(N) : "memory");
}
__device__ __forceinline__ void ldsm4(uint32_t* r, uint32_t addr) {
    asm volatile("ldmatrix.sync.aligned.m8n8.x4.shared.b16 {%0,%1,%2,%3}, [%4];"
                 : "=r"(r[0]), "=r"(r[1]), "=r"(r[2]), "=r"(r[3]) : "r"(addr));
}
__device__ __forceinline__ void ldsm4t(uint32_t* r, uint32_t addr) {
    asm volatile("ldmatrix.sync.aligned.m8n8.x4.trans.shared.b16 {%0,%1,%2,%3}, [%4];"
                 : "=r"(r[0]), "=r"(r[1]), "=r"(r[2]), "=r"(r[3]) : "r"(addr));
}
__device__ __forceinline__ void mma16816(float* c, const uint32_t* a, const uint32_t* b) {
    asm volatile("mma.sync.aligned.m16n8k16.row.col.f32.bf16.bf16.f32 "
                 "{%0,%1,%2,%3}, {%4,%5,%6,%7}, {%8,%9}, {%0,%1,%2,%3};"
                 : "+f"(c[0]), "+f"(c[1]), "+f"(c[2]), "+f"(c[3])
                 : "r"(a[0]), "r"(a[1]), "r"(a[2]), "r"(a[3]),
                   "r"(b[0]), "r"(b[1]));
}
__device__ __forceinline__ uint32_t packbf(__nv_bfloat16 x, __nv_bfloat16 y) {
    __nv_bfloat162 t = __halves2bfloat162(x, y);
    return *(uint32_t*)&t;
}

// ---------------------------------------------------------------------------
// Conversion kernels
// ---------------------------------------------------------------------------
__global__ void k_conv_x(const float* __restrict__ src, int n4)
{
    int i = blockIdx.x * blockDim.x + threadIdx.x;
    if (i >= n4) return;
    float4 v = ((const float4*)src)[i];
    __nv_bfloat16 h0 = __float2bfloat16(v.x), h1 = __float2bfloat16(v.y);
    __nv_bfloat16 h2 = __float2bfloat16(v.z), h3 = __float2bfloat16(v.w);
    __nv_bfloat16 l0 = __float2bfloat16(v.x - __bfloat162float(h0));
    __nv_bfloat16 l1 = __float2bfloat16(v.y - __bfloat162float(h1));
    __nv_bfloat16 l2 = __float2bfloat16(v.z - __bfloat162float(h2));
    __nv_bfloat16 l3 = __float2bfloat16(v.w - __bfloat162float(h3));
    ((__nv_bfloat162*)g_xh)[2 * i]     = __halves2bfloat162(h0, h1);
    ((__nv_bfloat162*)g_xh)[2 * i + 1] = __halves2bfloat162(h2, h3);
    ((__nv_bfloat162*)g_xl)[2 * i]     = __halves2bfloat162(l0, l1);
    ((__nv_bfloat162*)g_xl)[2 * i + 1] = __halves2bfloat162(l2, l3);
}

// W[h][d][e] (per part) -> g_wth/g_wtl[(p,h,e)][d]  (transpose into K-major)
__global__ void k_conv_wqkv(const float* __restrict__ Wq,
                            const float* __restrict__ Wk,
                            const float* __restrict__ Wv)
{
    __shared__ float sm[64 * 65];
    const int d0 = blockIdx.x * 64, h = blockIdx.y, p = blockIdx.z;
    const float* W = (p == 0) ? Wq : (p == 1) ? Wk : Wv;
    const int tid = threadIdx.x;
    #pragma unroll
    for (int t = 0; t < 16; t++) {
        int idx = tid + t * 256;
        int r = idx >> 6, e = idx & 63;
        sm[r * 65 + e] = W[((size_t)h * Dd + d0 + r) * HD + e];
    }
    __syncthreads();
    #pragma unroll
    for (int t = 0; t < 16; t++) {
        int idx = tid + t * 256;
        int e = idx >> 6, r = idx & 63;
        float v = sm[r * 65 + e];
        __nv_bfloat16 hi = __float2bfloat16(v);
        __nv_bfloat16 lo = __float2bfloat16(v - __bfloat162float(hi));
        size_t n = (size_t)p * 1024 + h * 64 + e;
        g_wth[n * Dd + d0 + r] = hi;
        g_wtl[n * Dd + d0 + r] = lo;
    }
}

// Wp[k][n] -> g_wph/g_wpl[n][k]
__global__ void k_conv_wp(const float* __restrict__ Wp)
{
    __shared__ float sm[64 * 65];
    const int n0 = blockIdx.x * 64, k0 = blockIdx.y * 64;
    const int tid = threadIdx.x;
    #pragma unroll
    for (int t = 0; t < 16; t++) {
        int idx = tid + t * 256;
        int r = idx >> 6, e = idx & 63;
        sm[r * 65 + e] = Wp[(size_t)(k0 + r) * Dd + n0 + e];
    }
    __syncthreads();
    #pragma unroll
    for (int t = 0; t < 16; t++) {
        int idx = tid + t * 256;
        int e = idx >> 6, r = idx & 63;
        float v = sm[r * 65 + e];
        __nv_bfloat16 hi = __float2bfloat16(v);
        __nv_bfloat16 lo = __float2bfloat16(v - __bfloat162float(hi));
        size_t n = (size_t)(n0 + e);
        g_wph[n * Dd + k0 + r] = hi;
        g_wpl[n * Dd + k0 + r] = lo;
    }
}

__global__ void k_bias(const float* __restrict__ bq, const float* __restrict__ bk,
                       const float* __restrict__ bv)
{
    int i = blockIdx.x * 256 + threadIdx.x;
    if (i < Nqkv)
        g_bias[i] = (i < 1024) ? bq[i] : (i < 2048) ? bk[i - 1024] : bv[i - 2048];
}

// ---------------------------------------------------------------------------
// mma.sync bf16 split-precision GEMM (validated R9): D += aH*bH + aH*bL + aL*bH
// CTA tile 128x128, BK=32, 128 threads = 4 warps (2m x 2n), warp tile 64x64.
// MODE 1 epilogue: q is pre-scaled by 1/8 (folded softmax scale).
// ---------------------------------------------------------------------------
constexpr int GK = 1024;
constexpr int BK = 32;
constexpr int NCHUNK = GK / BK;                 // 32
constexpr int TILE_B = 128 * BK * 2;            // 8192
constexpr int STAGE_B = 4 * TILE_B;             // 32768
constexpr int GEMM_SMEM = 2 * STAGE_B;          // 65536

__device__ __forceinline__ uint32_t tswz(int row, int c) {
    return (uint32_t)(row * 64 + ((c ^ (row & 3)) << 4));
}

template<int MODE>
__global__ __launch_bounds__(128)
void gemm_bf16x3(const float* __restrict__ bias_p, float* __restrict__ out)
{
    const __nv_bfloat16* Ah = (MODE == 0) ? g_oh : g_xh;
    const __nv_bfloat16* Al = (MODE == 0) ? g_ol : g_xl;
    const __nv_bfloat16* Bh = (MODE == 0) ? g_wph : g_wth;
    const __nv_bfloat16* Bl = (MODE == 0) ? g_wpl : g_wtl;
    const float* bias = (MODE == 0) ? bias_p : g_bias;

    extern __shared__ __align__(128) char smem[];
    const uint32_t sb = s2u(smem);
    const int tid = threadIdx.x;
    const int wid = tid >> 5, lane = tid & 31;
    const int warp_m = wid & 1;
    const int warp_n = wid >> 1;
    const int m0 = blockIdx.y * 128, n0 = blockIdx.x * 128;

    float acc[4][8][4];
    #pragma unroll
    for (int i = 0; i < 4; i++)
        #pragma unroll
        for (int j = 0; j < 8; j++)
            #pragma unroll
            for (int r = 0; r < 4; r++) acc[i][j][r] = 0.f;

    auto load_chunk = [&](int stage, int kc) {
        uint32_t sbase = sb + stage * STAGE_B;
        #pragma unroll
        for (int t4 = 0; t4 < 4; t4++) {
            const __nv_bfloat16* base =
                (t4 == 0) ? Ah : (t4 == 1) ? Al : (t4 == 2) ? Bh : Bl;
            const int r0 = (t4 < 2) ? m0 : n0;
            const uint32_t tbase = sbase + t4 * TILE_B;
            #pragma unroll
            for (int v = 0; v < 4; v++) {
                int id = tid + v * 128;
                int row = id >> 2, c = id & 3;
                const void* src = base + (size_t)(r0 + row) * GK + kc * BK + c * 8;
                cpasync16(tbase + tswz(row, c), src);
            }
        }
        cpcommit();
    };

    const int a_row = warp_m * 64 + (lane & 15);
    const int a_cb  = lane >> 4;
    const int b_j   = lane >> 3;
    const int b_row = warp_n * 64 + ((b_j >> 1) << 3) + (lane & 7);
    const int b_cb  = b_j & 1;

    load_chunk(0, 0);

    for (int i = 0; i < NCHUNK; i++) {
        const int s = i & 1;
        if (i + 1 < NCHUNK) {
            load_chunk(1 - s, i + 1);
            cpwait<1>();
        } else {
            cpwait<0>();
        }
        __syncthreads();

        const uint32_t tAh = sb + s * STAGE_B;
        const uint32_t tAl = tAh + TILE_B;
        const uint32_t tBh = tAh + 2 * TILE_B;
        const uint32_t tBl = tAh + 3 * TILE_B;

        #pragma unroll
        for (int ks = 0; ks < 2; ks++) {
            uint32_t ah[4][4], al[4][4];
            #pragma unroll
            for (int mt = 0; mt < 4; mt++) {
                const uint32_t off = tswz(a_row + mt * 16, ks * 2 + a_cb);
                ldsm4(ah[mt], tAh + off);
                ldsm4(al[mt], tAl + off);
            }
            #pragma unroll
            for (int np = 0; np < 4; np++) {
                const uint32_t off = tswz(b_row + np * 16, ks * 2 + b_cb);
                uint32_t bh[4], bl[4];
                ldsm4(bh, tBh + off);
                ldsm4(bl, tBl + off);
                #pragma unroll
                for (int mt = 0; mt < 4; mt++) {
                    #pragma unroll
                    for (int nt = 0; nt < 2; nt++) {
                        float* c = acc[mt][np * 2 + nt];
                        mma16816(c, ah[mt], &bh[nt * 2]);
                        mma16816(c, ah[mt], &bl[nt * 2]);
                        mma16816(c, al[mt], &bh[nt * 2]);
                    }
                }
            }
        }
        __syncthreads();
    }

    const int g = lane >> 2, t2 = (lane & 3) * 2;
    #pragma unroll
    for (int mt = 0; mt < 4; mt++) {
        #pragma unroll
        for (int nt = 0; nt < 8; nt++) {
            const int ncol = n0 + warp_n * 64 + nt * 8 + t2;
            #pragma unroll
            for (int rh = 0; rh < 2; rh++) {
                const int m = m0 + warp_m * 64 + mt * 16 + g + rh * 8;
                float vx = acc[mt][nt][rh * 2 + 0] + bias[ncol];
                float vy = acc[mt][nt][rh * 2 + 1] + bias[ncol + 1];
                if (MODE == 0) {
                    float2 v; v.x = vx; v.y = vy;
                    *(float2*)&out[(size_t)m * Dd + ncol] = v;
                } else {
                    const int part = ncol >> 10;
                    if (part == 0) { vx *= 0.125f; vy *= 0.125f; }  // fold 1/sqrt(64) into q
                    const int nn = ncol & 1023;
                    const int h = nn >> 6, e = nn & 63;
                    const int b = m >> 11, s_ = m & 2047;
                    __nv_bfloat16 hx = __float2bfloat16(vx);
                    __nv_bfloat16 hy = __float2bfloat16(vy);
                    __nv_bfloat16 lx = __float2bfloat16(vx - __bfloat162float(hx));
                    __nv_bfloat16 ly = __float2bfloat16(vy - __bfloat162float(hy));
                    __nv_bfloat16* dh = (part == 0) ? g_qh : (part == 1) ? g_kh : g_vh;
                    __nv_bfloat16* dl = (part == 0) ? g_ql : (part == 1) ? g_kl : g_vl;
                    size_t idx = ((size_t)(b * Hh + h) * Ss + s_) * HD + e;
                    *(__nv_bfloat162*)&dh[idx] = __halves2bfloat162(hx, hy);
                    *(__nv_bfloat162*)&dl[idx] = __halves2bfloat162(lx, ly);
                }
            }
        }
    }
}

// ---------------------------------------------------------------------------
// Flash attention on mma.sync, split-precision (3-term) QK^T and PV.
// R11: 32-key stages (was 64) -> 64KB smem -> 3 CTAs/SM for phase-latency
// hiding. 4 warps x 32 q-rows. q pre-scaled (no per-element scale here).
// ---------------------------------------------------------------------------
constexpr int AQT = 128, AKT = 32;
constexpr int AQ_B = 128 * 128;
constexpr int AT_B = 32 * 128;         // 4096
constexpr int ASTAGE_B = 4 * AT_B;     // 16384
constexpr int ATT_SMEM = 2 * AQ_B + 2 * ASTAGE_B;   // 65536

__device__ __forceinline__ uint32_t swz128(int row, int c) {
    return (uint32_t)(row * 128 + ((c ^ (row & 7)) << 4));
}

__global__ __launch_bounds__(128, 3) void attn_mma()
{
    extern __shared__ __align__(128) char smem[];
    const uint32_t sb = s2u(smem);
    const uint32_t sQH = sb, sQL = sb + AQ_B;
    const int tid = threadIdx.x, wid = tid >> 5, lane = tid & 31;
    const int bh = blockIdx.y;
    const int qi = 15 - (int)blockIdx.x;       // heavy tiles first
    const int q0 = qi * AQT;
    const int nkt = 4 * qi + 4;                // 32-key tiles

    const __nv_bfloat16* qh = g_qh + (size_t)bh * Ss * HD;
    const __nv_bfloat16* ql = g_ql + (size_t)bh * Ss * HD;
    const __nv_bfloat16* kh = g_kh + (size_t)bh * Ss * HD;
    const __nv_bfloat16* kl = g_kl + (size_t)bh * Ss * HD;
    const __nv_bfloat16* vh = g_vh + (size_t)bh * Ss * HD;
    const __nv_bfloat16* vl = g_vl + (size_t)bh * Ss * HD;

    // Q hi/lo -> smem (joins first commit group)
    #pragma unroll
    for (int v = 0; v < 8; v++) {
        int id = tid + v * 128;           // 0..1023
        int row = id >> 3, c = id & 7;
        cpasync16(sQH + swz128(row, c), qh + (size_t)(q0 + row) * HD + c * 8);
        cpasync16(sQL + swz128(row, c), ql + (size_t)(q0 + row) * HD + c * 8);
    }

    auto load_kv = [&](int stage, int kt) {
        const int k0 = kt * AKT;
        uint32_t base = sb + 2 * AQ_B + stage * ASTAGE_B;
        #pragma unroll
        for (int v = 0; v < 2; v++) {
            int id = tid + v * 128;       // 0..255
            int row = id >> 3, c = id & 7;
            uint32_t so = swz128(row, c);
            cpasync16(base + so,            kh + (size_t)(k0 + row) * HD + c * 8);
            cpasync16(base + AT_B + so,     kl + (size_t)(k0 + row) * HD + c * 8);
            cpasync16(base + 2 * AT_B + so, vh + (size_t)(k0 + row) * HD + c * 8);
            cpasync16(base + 3 * AT_B + so, vl + (size_t)(k0 + row) * HD + c * 8);
        }
        cpcommit();
    };

    load_kv(0, 0);

    float oacc[2][8][4];                 // [mt][hd n8][frag]
    #pragma unroll
    for (int mt = 0; mt < 2; mt++)
        #pragma unroll
        for (int j = 0; j < 8; j++)
            #pragma unroll
            for (int r = 0; r < 4; r++) oacc[mt][j][r] = 0.f;
    float mm[4] = {-1e30f, -1e30f, -1e30f, -1e30f};   // [mt*2+rh]
    float ll[4] = {0.f, 0.f, 0.f, 0.f};

    const int g = lane >> 2, t2 = (lane & 3) * 2;
    const int a_row = wid * 32 + (lane & 15);          // + mt*16
    const int a_cb  = lane >> 4;
    const int b_j   = lane >> 3;
    const int b_row = ((b_j >> 1) << 3) + (lane & 7);
    const int b_cb  = b_j & 1;
    const int vb_row = ((b_j & 1) << 3) + (lane & 7);
    const int vb_ch  = b_j >> 1;
    const int wrow_max = q0 + wid * 32 + 31;
    const int row0g = q0 + wid * 32 + g;

    for (int kt = 0; kt < nkt; kt++) {
        const int s = kt & 1;
        if (kt + 1 < nkt) { load_kv(1 - s, kt + 1); cpwait<1>(); }
        else              { cpwait<0>(); }
        __syncthreads();

        const int k0 = kt * AKT;
        const uint32_t bKH = sb + 2 * AQ_B + s * ASTAGE_B;
        const uint32_t bKL = bKH + AT_B;
        const uint32_t bVH = bKH + 2 * AT_B;
        const uint32_t bVL = bKH + 3 * AT_B;

        if (k0 <= wrow_max) {
            // S = Q K^T (split 3-term), 32 rows x 32 keys
            float sacc[2][4][4];
            #pragma unroll
            for (int mt = 0; mt < 2; mt++)
                #pragma unroll
                for (int j = 0; j < 4; j++)
                    #pragma unroll
                    for (int r = 0; r < 4; r++) sacc[mt][j][r] = 0.f;

            #pragma unroll
            for (int ks = 0; ks < 4; ks++) {
                uint32_t aH[2][4], aL[2][4];
                #pragma unroll
                for (int mt = 0; mt < 2; mt++) {
                    const uint32_t aoff = swz128(a_row + mt * 16, ks * 2 + a_cb);
                    ldsm4(aH[mt], sQH + aoff);
                    ldsm4(aL[mt], sQL + aoff);
                }
                #pragma unroll
                for (int nt16 = 0; nt16 < 2; nt16++) {
                    const uint32_t boff = swz128(nt16 * 16 + b_row, ks * 2 + b_cb);
                    uint32_t bH[4], bL[4];
                    ldsm4(bH, bKH + boff);
                    ldsm4(bL, bKL + boff);
                    #pragma unroll
                    for (int mt = 0; mt < 2; mt++) {
                        #pragma unroll
                        for (int i2 = 0; i2 < 2; i2++) {
                            float* c = sacc[mt][nt16 * 2 + i2];
                            mma16816(c, aH[mt], &bH[i2 * 2]);
                            mma16816(c, aH[mt], &bL[i2 * 2]);
                            mma16816(c, aL[mt], &bH[i2 * 2]);
                        }
                    }
                }
            }

            // causal mask (diagonal tiles only; q pre-scaled)
            const bool dm = (kt >= 4 * qi);
            if (dm) {
                #pragma unroll
                for (int mt = 0; mt < 2; mt++)
                    #pragma unroll
                    for (int nt = 0; nt < 4; nt++)
                        #pragma unroll
                        for (int c = 0; c < 4; c++) {
                            int row = row0g + mt * 16 + ((c >> 1) << 3);
                            int key = k0 + nt * 8 + t2 + (c & 1);
                            if (key > row) sacc[mt][nt][c] = -1e30f;
                        }
            }

            // online softmax: 4 row-states (mt x row-half)
            #pragma unroll
            for (int mt = 0; mt < 2; mt++) {
                float rm0 = -1e30f, rm1 = -1e30f;
                #pragma unroll
                for (int nt = 0; nt < 4; nt++) {
                    rm0 = fmaxf(rm0, fmaxf(sacc[mt][nt][0], sacc[mt][nt][1]));
                    rm1 = fmaxf(rm1, fmaxf(sacc[mt][nt][2], sacc[mt][nt][3]));
                }
                rm0 = fmaxf(rm0, __shfl_xor_sync(0xffffffffu, rm0, 1));
                rm0 = fmaxf(rm0, __shfl_xor_sync(0xffffffffu, rm0, 2));
                rm1 = fmaxf(rm1, __shfl_xor_sync(0xffffffffu, rm1, 1));
                rm1 = fmaxf(rm1, __shfl_xor_sync(0xffffffffu, rm1, 2));
                const float mn0 = fmaxf(mm[mt * 2 + 0], rm0);
                const float mn1 = fmaxf(mm[mt * 2 + 1], rm1);
                const float al0 = __expf(mm[mt * 2 + 0] - mn0);
                const float al1 = __expf(mm[mt * 2 + 1] - mn1);
                mm[mt * 2 + 0] = mn0; mm[mt * 2 + 1] = mn1;
                float rs0 = 0.f, rs1 = 0.f;
                #pragma unroll
                for (int nt = 0; nt < 4; nt++) {
                    float p0 = __expf(sacc[mt][nt][0] - mn0);
                    float p1 = __expf(sacc[mt][nt][1] - mn0);
                    float p2 = __expf(sacc[mt][nt][2] - mn1);
                    float p3 = __expf(sacc[mt][nt][3] - mn1);
                    sacc[mt][nt][0] = p0; sacc[mt][nt][1] = p1;
                    sacc[mt][nt][2] = p2; sacc[mt][nt][3] = p3;
                    rs0 += p0 + p1; rs1 += p2 + p3;
                }
                rs0 += __shfl_xor_sync(0xffffffffu, rs0, 1);
                rs0 += __shfl_xor_sync(0xffffffffu, rs0, 2);
                rs1 += __shfl_xor_sync(0xffffffffu, rs1, 1);
                rs1 += __shfl_xor_sync(0xffffffffu, rs1, 2);
                ll[mt * 2 + 0] = ll[mt * 2 + 0] * al0 + rs0;
                ll[mt * 2 + 1] = ll[mt * 2 + 1] * al1 + rs1;
                #pragma unroll
                for (int nt = 0; nt < 8; nt++) {
                    oacc[mt][nt][0] *= al0; oacc[mt][nt][1] *= al0;
                    oacc[mt][nt][2] *= al1; oacc[mt][nt][3] *= al1;
                }
            }

            // O += P V  (P split hi/lo; V split hi/lo; 3-term)
            #pragma unroll
            for (int ks2 = 0; ks2 < 2; ks2++) {
                uint32_t aP[2][4], aPl[2][4];
                #pragma unroll
                for (int mt = 0; mt < 2; mt++) {
                    #pragma unroll
                    for (int half = 0; half < 2; half++) {
                        const int nt = 2 * ks2 + half;
                        __nv_bfloat16 h00 = __float2bfloat16(sacc[mt][nt][0]);
                        __nv_bfloat16 h01 = __float2bfloat16(sacc[mt][nt][1]);
                        __nv_bfloat16 h10 = __float2bfloat16(sacc[mt][nt][2]);
                        __nv_bfloat16 h11 = __float2bfloat16(sacc[mt][nt][3]);
                        aP[mt][half * 2 + 0] = packbf(h00, h01);
                        aP[mt][half * 2 + 1] = packbf(h10, h11);
                        __nv_bfloat16 e00 = __float2bfloat16(sacc[mt][nt][0] - __bfloat162float(h00));
                        __nv_bfloat16 e01 = __float2bfloat16(sacc[mt][nt][1] - __bfloat162float(h01));
                        __nv_bfloat16 e10 = __float2bfloat16(sacc[mt][nt][2] - __bfloat162float(h10));
                        __nv_bfloat16 e11 = __float2bfloat16(sacc[mt][nt][3] - __bfloat162float(h11));
                        aPl[mt][half * 2 + 0] = packbf(e00, e01);
                        aPl[mt][half * 2 + 1] = packbf(e10, e11);
                    }
                }
                #pragma unroll
                for (int nt16 = 0; nt16 < 4; nt16++) {
                    const uint32_t voff =
                        swz128(ks2 * 16 + vb_row, nt16 * 2 + vb_ch);
                    uint32_t vH[4], vL[4];
                    ldsm4t(vH, bVH + voff);
                    ldsm4t(vL, bVL + voff);
                    #pragma unroll
                    for (int mt = 0; mt < 2; mt++) {
                        #pragma unroll
                        for (int i2 = 0; i2 < 2; i2++) {
                            float* c = oacc[mt][nt16 * 2 + i2];
                            mma16816(c, aP[mt], &vH[i2 * 2]);
                            mma16816(c, aP[mt], &vL[i2 * 2]);
                            mma16816(c, aPl[mt], &vH[i2 * 2]);
                        }
                    }
                }
            }
        }
        __syncthreads();
    }

    // Epilogue: normalize, write bf16 hi/lo into g_oh/g_ol [B,S,D]
    const int b = bh >> 4, h = bh & 15;
    #pragma unroll
    for (int mt = 0; mt < 2; mt++) {
        const float inv0 = 1.f / ll[mt * 2 + 0];
        const float inv1 = 1.f / ll[mt * 2 + 1];
        const int row0 = q0 + wid * 32 + mt * 16 + g;
        #pragma unroll
        for (int nt = 0; nt < 8; nt++) {
            const int col = h * HD + nt * 8 + t2;
            #pragma unroll
            for (int rh = 0; rh < 2; rh++) {
                const float inv = rh ? inv1 : inv0;
                const int row = row0 + rh * 8;
                float vx = oacc[mt][nt][rh * 2 + 0] * inv;
                float vy = oacc[mt][nt][rh * 2 + 1] * inv;
                __nv_bfloat16 hx = __float2bfloat16(vx);
                __nv_bfloat16 hy = __float2bfloat16(vy);
                __nv_bfloat16 lx = __float2bfloat16(vx - __bfloat162float(hx));
                __nv_bfloat16 ly = __float2bfloat16(vy - __bfloat162float(hy));
                size_t idx = (size_t)(b * Ss + row) * Dd + col;
                *(__nv_bfloat162*)&g_oh[idx] = __halves2bfloat162(hx, hy);
                *(__nv_bfloat162*)&g_ol[idx] = __halves2bfloat162(lx, ly);
            }
        }
    }
}

// ---------------------------------------------------------------------------
// Launch — only harness pointers cross the host/device boundary
// ---------------------------------------------------------------------------
extern "C" void kernel_launch(void* const* d_in, const int* in_sizes, int n_in,
                              void* d_out, int out_size)
{
    const float* x  = (const float*)d_in[0];
    const float* Wq = (const float*)d_in[1];
    const float* bq = (const float*)d_in[2];
    const float* Wk = (const float*)d_in[3];
    const float* bk = (const float*)d_in[4];
    const float* Wv = (const float*)d_in[5];
    const float* bv = (const float*)d_in[6];
    const float* Wp = (const float*)d_in[7];
    const float* bp = (const float*)d_in[8];
    float* out = (float*)d_out;

    cudaFuncSetAttribute(gemm_bf16x3<0>,
                         cudaFuncAttributeMaxDynamicSharedMemorySize, GEMM_SMEM);
    cudaFuncSetAttribute(gemm_bf16x3<1>,
                         cudaFuncAttributeMaxDynamicSharedMemorySize, GEMM_SMEM);
    cudaFuncSetAttribute(attn_mma,
                         cudaFuncAttributeMaxDynamicSharedMemorySize, ATT_SMEM);

    // Conversions
    const int n4 = Mtot * Dd / 4;
    k_conv_x<<<(n4 + 255) / 256, 256>>>(x, n4);
    k_conv_wqkv<<<dim3(16, 16, 3), 256>>>(Wq, Wk, Wv);
    k_conv_wp<<<dim3(16, 16), 256>>>(Wp);
    k_bias<<<12, 256>>>(bq, bk, bv);

    // QKV projection (q pre-scaled by 1/8; q/k/v hi/lo into [B,H,S,HD])
    gemm_bf16x3<1><<<dim3(24, 64), 128, GEMM_SMEM>>>(nullptr, nullptr);

    // Attention (mma.sync, split precision, 32-key stages, 3 CTAs/SM)
    attn_mma<<<dim3(16, 64), 128, ATT_SMEM>>>();

    // Output projection
    gemm_bf16x3<0><<<dim3(8, 64), 128, GEMM_SMEM>>>(bp, out);
}

// round 13
// speedup vs baseline: 1.0450x; 1.0450x over previous
#include <cuda_runtime.h>
#include <cuda_bf16.h>
#include <cstdint>

// ---------------------------------------------------------------------------
// Problem constants
// ---------------------------------------------------------------------------
constexpr int Bc = 4;
constexpr int Ss = 2048;
constexpr int Dd = 1024;
constexpr int Hh = 16;
constexpr int HD = 64;
constexpr int Mtot = Bc * Ss;          // 8192
constexpr int Nqkv = 3 * Dd;           // 3072

// ---------------------------------------------------------------------------
// Scratch (device globals — referenced ONLY from device code)
// ---------------------------------------------------------------------------
__device__ __nv_bfloat16 g_qh[(size_t)Bc * Hh * Ss * HD];  // [B,H,S,HD] (pre-scaled 1/8)
__device__ __nv_bfloat16 g_ql[(size_t)Bc * Hh * Ss * HD];
__device__ __nv_bfloat16 g_kh[(size_t)Bc * Hh * Ss * HD];
__device__ __nv_bfloat16 g_kl[(size_t)Bc * Hh * Ss * HD];
__device__ __nv_bfloat16 g_vh[(size_t)Bc * Hh * Ss * HD];
__device__ __nv_bfloat16 g_vl[(size_t)Bc * Hh * Ss * HD];

__device__ __nv_bfloat16 g_xh[(size_t)Mtot * Dd];
__device__ __nv_bfloat16 g_xl[(size_t)Mtot * Dd];
__device__ __nv_bfloat16 g_oh[(size_t)Mtot * Dd];          // attention out hi/lo
__device__ __nv_bfloat16 g_ol[(size_t)Mtot * Dd];
__device__ __nv_bfloat16 g_wth[(size_t)Nqkv * Dd];         // [N=3072][K=1024] (W^T)
__device__ __nv_bfloat16 g_wtl[(size_t)Nqkv * Dd];
__device__ __nv_bfloat16 g_wph[(size_t)Dd * Dd];           // [N=1024][K=1024] (Wp^T)
__device__ __nv_bfloat16 g_wpl[(size_t)Dd * Dd];
__device__ float g_bias[Nqkv];

// ---------------------------------------------------------------------------
// PTX helpers (baseline ISA only — assembles at .target sm_100)
// ---------------------------------------------------------------------------
__device__ __forceinline__ uint32_t s2u(const void* p) {
    uint32_t a;
    asm("{ .reg .u64 t; cvta.to.shared.u64 t, %1; cvt.u32.u64 %0, t; }"
        : "=r"(a) : "l"(p));
    return a;
}
__device__ __forceinline__ void cpasync16(uint32_t dst, const void* src) {
    asm volatile("cp.async.cg.shared.global [%0], [%1], 16;"
                 :: "r"(dst), "l"(src) : "memory");
}
__device__ __forceinline__ void cpcommit() {
    asm volatile("cp.async.commit_group;" ::: "memory");
}
template<int N> __device__ __forceinline__ void cpwait() {
    asm volatile("cp.async.wait_group %0;" :: "n"(N) : "memory");
}
__device__ __forceinline__ void ldsm4(uint32_t* r, uint32_t addr) {
    asm volatile("ldmatrix.sync.aligned.m8n8.x4.shared.b16 {%0,%1,%2,%3}, [%4];"
                 : "=r"(r[0]), "=r"(r[1]), "=r"(r[2]), "=r"(r[3]) : "r"(addr));
}
__device__ __forceinline__ void ldsm4t(uint32_t* r, uint32_t addr) {
    asm volatile("ldmatrix.sync.aligned.m8n8.x4.trans.shared.b16 {%0,%1,%2,%3}, [%4];"
                 : "=r"(r[0]), "=r"(r[1]), "=r"(r[2]), "=r"(r[3]) : "r"(addr));
}
__device__ __forceinline__ void mma16816(float* c, const uint32_t* a, const uint32_t* b) {
    asm volatile("mma.sync.aligned.m16n8k16.row.col.f32.bf16.bf16.f32 "
                 "{%0,%1,%2,%3}, {%4,%5,%6,%7}, {%8,%9}, {%0,%1,%2,%3};"
                 : "+f"(c[0]), "+f"(c[1]), "+f"(c[2]), "+f"(c[3])
                 : "r"(a[0]), "r"(a[1]), "r"(a[2]), "r"(a[3]),
                   "r"(b[0]), "r"(b[1]));
}
__device__ __forceinline__ uint32_t packbf(__nv_bfloat16 x, __nv_bfloat16 y) {
    __nv_bfloat162 t = __halves2bfloat162(x, y);
    return *(uint32_t*)&t;
}

// ---------------------------------------------------------------------------
// Conversion kernels
// ---------------------------------------------------------------------------
__global__ void k_conv_x(const float* __restrict__ src, int n4)
{
    int i = blockIdx.x * blockDim.x + threadIdx.x;
    if (i >= n4) return;
    float4 v = ((const float4*)src)[i];
    __nv_bfloat16 h0 = __float2bfloat16(v.x), h1 = __float2bfloat16(v.y);
    __nv_bfloat16 h2 = __float2bfloat16(v.z), h3 = __float2bfloat16(v.w);
    __nv_bfloat16 l0 = __float2bfloat16(v.x - __bfloat162float(h0));
    __nv_bfloat16 l1 = __float2bfloat16(v.y - __bfloat162float(h1));
    __nv_bfloat16 l2 = __float2bfloat16(v.z - __bfloat162float(h2));
    __nv_bfloat16 l3 = __float2bfloat16(v.w - __bfloat162float(h3));
    ((__nv_bfloat162*)g_xh)[2 * i]     = __halves2bfloat162(h0, h1);
    ((__nv_bfloat162*)g_xh)[2 * i + 1] = __halves2bfloat162(h2, h3);
    ((__nv_bfloat162*)g_xl)[2 * i]     = __halves2bfloat162(l0, l1);
    ((__nv_bfloat162*)g_xl)[2 * i + 1] = __halves2bfloat162(l2, l3);
}

// W[h][d][e] (per part) -> g_wth/g_wtl[(p,h,e)][d]  (transpose into K-major)
__global__ void k_conv_wqkv(const float* __restrict__ Wq,
                            const float* __restrict__ Wk,
                            const float* __restrict__ Wv)
{
    __shared__ float sm[64 * 65];
    const int d0 = blockIdx.x * 64, h = blockIdx.y, p = blockIdx.z;
    const float* W = (p == 0) ? Wq : (p == 1) ? Wk : Wv;
    const int tid = threadIdx.x;
    #pragma unroll
    for (int t = 0; t < 16; t++) {
        int idx = tid + t * 256;
        int r = idx >> 6, e = idx & 63;
        sm[r * 65 + e] = W[((size_t)h * Dd + d0 + r) * HD + e];
    }
    __syncthreads();
    #pragma unroll
    for (int t = 0; t < 16; t++) {
        int idx = tid + t * 256;
        int e = idx >> 6, r = idx & 63;
        float v = sm[r * 65 + e];
        __nv_bfloat16 hi = __float2bfloat16(v);
        __nv_bfloat16 lo = __float2bfloat16(v - __bfloat162float(hi));
        size_t n = (size_t)p * 1024 + h * 64 + e;
        g_wth[n * Dd + d0 + r] = hi;
        g_wtl[n * Dd + d0 + r] = lo;
    }
}

// Wp[k][n] -> g_wph/g_wpl[n][k]
__global__ void k_conv_wp(const float* __restrict__ Wp)
{
    __shared__ float sm[64 * 65];
    const int n0 = blockIdx.x * 64, k0 = blockIdx.y * 64;
    const int tid = threadIdx.x;
    #pragma unroll
    for (int t = 0; t < 16; t++) {
        int idx = tid + t * 256;
        int r = idx >> 6, e = idx & 63;
        sm[r * 65 + e] = Wp[(size_t)(k0 + r) * Dd + n0 + e];
    }
    __syncthreads();
    #pragma unroll
    for (int t = 0; t < 16; t++) {
        int idx = tid + t * 256;
        int e = idx >> 6, r = idx & 63;
        float v = sm[r * 65 + e];
        __nv_bfloat16 hi = __float2bfloat16(v);
        __nv_bfloat16 lo = __float2bfloat16(v - __bfloat162float(hi));
        size_t n = (size_t)(n0 + e);
        g_wph[n * Dd + k0 + r] = hi;
        g_wpl[n * Dd + k0 + r] = lo;
    }
}

__global__ void k_bias(const float* __restrict__ bq, const float* __restrict__ bk,
                       const float* __restrict__ bv)
{
    int i = blockIdx.x * 256 + threadIdx.x;
    if (i < Nqkv)
        g_bias[i] = (i < 1024) ? bq[i] : (i < 2048) ? bk[i - 1024] : bv[i - 2048];
}

// ---------------------------------------------------------------------------
// mma.sync bf16 split-precision GEMM (validated R9/R11): D += aH*bH+aH*bL+aL*bH
// CTA tile 128x128, BK=32, 128 threads = 4 warps (2m x 2n), warp tile 64x64.
// MODE 1 epilogue: q pre-scaled by 1/8 (folded softmax scale).
// ---------------------------------------------------------------------------
constexpr int GK = 1024;
constexpr int BK = 32;
constexpr int NCHUNK = GK / BK;                 // 32
constexpr int TILE_B = 128 * BK * 2;            // 8192
constexpr int STAGE_B = 4 * TILE_B;             // 32768
constexpr int GEMM_SMEM = 2 * STAGE_B;          // 65536

__device__ __forceinline__ uint32_t tswz(int row, int c) {
    return (uint32_t)(row * 64 + ((c ^ (row & 3)) << 4));
}

template<int MODE>
__global__ __launch_bounds__(128)
void gemm_bf16x3(const float* __restrict__ bias_p, float* __restrict__ out)
{
    const __nv_bfloat16* Ah = (MODE == 0) ? g_oh : g_xh;
    const __nv_bfloat16* Al = (MODE == 0) ? g_ol : g_xl;
    const __nv_bfloat16* Bh = (MODE == 0) ? g_wph : g_wth;
    const __nv_bfloat16* Bl = (MODE == 0) ? g_wpl : g_wtl;
    const float* bias = (MODE == 0) ? bias_p : g_bias;

    extern __shared__ __align__(128) char smem[];
    const uint32_t sb = s2u(smem);
    const int tid = threadIdx.x;
    const int wid = tid >> 5, lane = tid & 31;
    const int warp_m = wid & 1;
    const int warp_n = wid >> 1;
    const int m0 = blockIdx.y * 128, n0 = blockIdx.x * 128;

    float acc[4][8][4];
    #pragma unroll
    for (int i = 0; i < 4; i++)
        #pragma unroll
        for (int j = 0; j < 8; j++)
            #pragma unroll
            for (int r = 0; r < 4; r++) acc[i][j][r] = 0.f;

    auto load_chunk = [&](int stage, int kc) {
        uint32_t sbase = sb + stage * STAGE_B;
        #pragma unroll
        for (int t4 = 0; t4 < 4; t4++) {
            const __nv_bfloat16* base =
                (t4 == 0) ? Ah : (t4 == 1) ? Al : (t4 == 2) ? Bh : Bl;
            const int r0 = (t4 < 2) ? m0 : n0;
            const uint32_t tbase = sbase + t4 * TILE_B;
            #pragma unroll
            for (int v = 0; v < 4; v++) {
                int id = tid + v * 128;
                int row = id >> 2, c = id & 3;
                const void* src = base + (size_t)(r0 + row) * GK + kc * BK + c * 8;
                cpasync16(tbase + tswz(row, c), src);
            }
        }
        cpcommit();
    };

    const int a_row = warp_m * 64 + (lane & 15);
    const int a_cb  = lane >> 4;
    const int b_j   = lane >> 3;
    const int b_row = warp_n * 64 + ((b_j >> 1) << 3) + (lane & 7);
    const int b_cb  = b_j & 1;

    load_chunk(0, 0);

    for (int i = 0; i < NCHUNK; i++) {
        const int s = i & 1;
        if (i + 1 < NCHUNK) {
            load_chunk(1 - s, i + 1);
            cpwait<1>();
        } else {
            cpwait<0>();
        }
        __syncthreads();

        const uint32_t tAh = sb + s * STAGE_B;
        const uint32_t tAl = tAh + TILE_B;
        const uint32_t tBh = tAh + 2 * TILE_B;
        const uint32_t tBl = tAh + 3 * TILE_B;

        #pragma unroll
        for (int ks = 0; ks < 2; ks++) {
            uint32_t ah[4][4], al[4][4];
            #pragma unroll
            for (int mt = 0; mt < 4; mt++) {
                const uint32_t off = tswz(a_row + mt * 16, ks * 2 + a_cb);
                ldsm4(ah[mt], tAh + off);
                ldsm4(al[mt], tAl + off);
            }
            #pragma unroll
            for (int np = 0; np < 4; np++) {
                const uint32_t off = tswz(b_row + np * 16, ks * 2 + b_cb);
                uint32_t bh[4], bl[4];
                ldsm4(bh, tBh + off);
                ldsm4(bl, tBl + off);
                #pragma unroll
                for (int mt = 0; mt < 4; mt++) {
                    #pragma unroll
                    for (int nt = 0; nt < 2; nt++) {
                        float* c = acc[mt][np * 2 + nt];
                        mma16816(c, ah[mt], &bh[nt * 2]);
                        mma16816(c, ah[mt], &bl[nt * 2]);
                        mma16816(c, al[mt], &bh[nt * 2]);
                    }
                }
            }
        }
        __syncthreads();
    }

    const int g = lane >> 2, t2 = (lane & 3) * 2;
    #pragma unroll
    for (int mt = 0; mt < 4; mt++) {
        #pragma unroll
        for (int nt = 0; nt < 8; nt++) {
            const int ncol = n0 + warp_n * 64 + nt * 8 + t2;
            #pragma unroll
            for (int rh = 0; rh < 2; rh++) {
                const int m = m0 + warp_m * 64 + mt * 16 + g + rh * 8;
                float vx = acc[mt][nt][rh * 2 + 0] + bias[ncol];
                float vy = acc[mt][nt][rh * 2 + 1] + bias[ncol + 1];
                if (MODE == 0) {
                    float2 v; v.x = vx; v.y = vy;
                    *(float2*)&out[(size_t)m * Dd + ncol] = v;
                } else {
                    const int part = ncol >> 10;
                    if (part == 0) { vx *= 0.125f; vy *= 0.125f; }  // fold 1/sqrt(64) into q
                    const int nn = ncol & 1023;
                    const int h = nn >> 6, e = nn & 63;
                    const int b = m >> 11, s_ = m & 2047;
                    __nv_bfloat16 hx = __float2bfloat16(vx);
                    __nv_bfloat16 hy = __float2bfloat16(vy);
                    __nv_bfloat16 lx = __float2bfloat16(vx - __bfloat162float(hx));
                    __nv_bfloat16 ly = __float2bfloat16(vy - __bfloat162float(hy));
                    __nv_bfloat16* dh = (part == 0) ? g_qh : (part == 1) ? g_kh : g_vh;
                    __nv_bfloat16* dl = (part == 0) ? g_ql : (part == 1) ? g_kl : g_vl;
                    size_t idx = ((size_t)(b * Hh + h) * Ss + s_) * HD + e;
                    *(__nv_bfloat162*)&dh[idx] = __halves2bfloat162(hx, hy);
                    *(__nv_bfloat162*)&dl[idx] = __halves2bfloat162(lx, ly);
                }
            }
        }
    }
}

// ---------------------------------------------------------------------------
// Flash attention on mma.sync, split-precision (3-term) QK^T and PV.
// R13 (= R12 resubmit): validated R10 shape (64-key stages, 96KB smem,
// 2 CTA/SM, 4 warps x 32 q-rows) + q pre-scaled + hoisted mask branch.
// ---------------------------------------------------------------------------
constexpr int AQT = 128, AKT = 64;
constexpr int AQ_B = 128 * 128;
constexpr int AT_B = 64 * 128;
constexpr int ASTAGE_B = 4 * AT_B;
constexpr int ATT_SMEM = 2 * AQ_B + 2 * ASTAGE_B;   // 98304

__device__ __forceinline__ uint32_t swz128(int row, int c) {
    return (uint32_t)(row * 128 + ((c ^ (row & 7)) << 4));
}

__global__ __launch_bounds__(128) void attn_mma()
{
    extern __shared__ __align__(128) char smem[];
    const uint32_t sb = s2u(smem);
    const uint32_t sQH = sb, sQL = sb + AQ_B;
    const int tid = threadIdx.x, wid = tid >> 5, lane = tid & 31;
    const int bh = blockIdx.y;
    const int qi = 15 - (int)blockIdx.x;       // heavy tiles first
    const int q0 = qi * AQT;
    const int nkt = 2 * qi + 2;                // 64-key tiles

    const __nv_bfloat16* qh = g_qh + (size_t)bh * Ss * HD;
    const __nv_bfloat16* ql = g_ql + (size_t)bh * Ss * HD;
    const __nv_bfloat16* kh = g_kh + (size_t)bh * Ss * HD;
    const __nv_bfloat16* kl = g_kl + (size_t)bh * Ss * HD;
    const __nv_bfloat16* vh = g_vh + (size_t)bh * Ss * HD;
    const __nv_bfloat16* vl = g_vl + (size_t)bh * Ss * HD;

    // Q hi/lo -> smem (joins first commit group)
    #pragma unroll
    for (int v = 0; v < 8; v++) {
        int id = tid + v * 128;           // 0..1023
        int row = id >> 3, c = id & 7;
        cpasync16(sQH + swz128(row, c), qh + (size_t)(q0 + row) * HD + c * 8);
        cpasync16(sQL + swz128(row, c), ql + (size_t)(q0 + row) * HD + c * 8);
    }

    auto load_kv = [&](int stage, int kt) {
        const int k0 = kt * AKT;
        uint32_t base = sb + 2 * AQ_B + stage * ASTAGE_B;
        #pragma unroll
        for (int v = 0; v < 4; v++) {
            int id = tid + v * 128;       // 0..511
            int row = id >> 3, c = id & 7;
            uint32_t so = swz128(row, c);
            cpasync16(base + so,            kh + (size_t)(k0 + row) * HD + c * 8);
            cpasync16(base + AT_B + so,     kl + (size_t)(k0 + row) * HD + c * 8);
            cpasync16(base + 2 * AT_B + so, vh + (size_t)(k0 + row) * HD + c * 8);
            cpasync16(base + 3 * AT_B + so, vl + (size_t)(k0 + row) * HD + c * 8);
        }
        cpcommit();
    };

    load_kv(0, 0);

    float oacc[2][8][4];                 // [mt][hd n8][frag]
    #pragma unroll
    for (int mt = 0; mt < 2; mt++)
        #pragma unroll
        for (int j = 0; j < 8; j++)
            #pragma unroll
            for (int r = 0; r < 4; r++) oacc[mt][j][r] = 0.f;
    float mm[4] = {-1e30f, -1e30f, -1e30f, -1e30f};   // [mt*2+rh]
    float ll[4] = {0.f, 0.f, 0.f, 0.f};

    const int g = lane >> 2, t2 = (lane & 3) * 2;
    const int a_row = wid * 32 + (lane & 15);          // + mt*16
    const int a_cb  = lane >> 4;
    const int b_j   = lane >> 3;
    const int b_row = ((b_j >> 1) << 3) + (lane & 7);
    const int b_cb  = b_j & 1;
    const int vb_row = ((b_j & 1) << 3) + (lane & 7);
    const int vb_ch  = b_j >> 1;
    const int wrow_max = q0 + wid * 32 + 31;
    const int row0g = q0 + wid * 32 + g;

    for (int kt = 0; kt < nkt; kt++) {
        const int s = kt & 1;
        if (kt + 1 < nkt) { load_kv(1 - s, kt + 1); cpwait<1>(); }
        else              { cpwait<0>(); }
        __syncthreads();

        const int k0 = kt * AKT;
        const uint32_t bKH = sb + 2 * AQ_B + s * ASTAGE_B;
        const uint32_t bKL = bKH + AT_B;
        const uint32_t bVH = bKH + 2 * AT_B;
        const uint32_t bVL = bKH + 3 * AT_B;

        if (k0 <= wrow_max) {
            // S = Q K^T (split 3-term), 32 rows x 64 keys (q pre-scaled)
            float sacc[2][8][4];
            #pragma unroll
            for (int mt = 0; mt < 2; mt++)
                #pragma unroll
                for (int j = 0; j < 8; j++)
                    #pragma unroll
                    for (int r = 0; r < 4; r++) sacc[mt][j][r] = 0.f;

            #pragma unroll
            for (int ks = 0; ks < 4; ks++) {
                uint32_t aH[2][4], aL[2][4];
                #pragma unroll
                for (int mt = 0; mt < 2; mt++) {
                    const uint32_t aoff = swz128(a_row + mt * 16, ks * 2 + a_cb);
                    ldsm4(aH[mt], sQH + aoff);
                    ldsm4(aL[mt], sQL + aoff);
                }
                #pragma unroll
                for (int nt16 = 0; nt16 < 4; nt16++) {
                    const uint32_t boff = swz128(nt16 * 16 + b_row, ks * 2 + b_cb);
                    uint32_t bH[4], bL[4];
                    ldsm4(bH, bKH + boff);
                    ldsm4(bL, bKL + boff);
                    #pragma unroll
                    for (int mt = 0; mt < 2; mt++) {
                        #pragma unroll
                        for (int i2 = 0; i2 < 2; i2++) {
                            float* c = sacc[mt][nt16 * 2 + i2];
                            mma16816(c, aH[mt], &bH[i2 * 2]);
                            mma16816(c, aH[mt], &bL[i2 * 2]);
                            mma16816(c, aL[mt], &bH[i2 * 2]);
                        }
                    }
                }
            }

            // causal mask (diagonal tiles only)
            const bool dm = (kt >= 2 * qi);
            if (dm) {
                #pragma unroll
                for (int mt = 0; mt < 2; mt++)
                    #pragma unroll
                    for (int nt = 0; nt < 8; nt++)
                        #pragma unroll
                        for (int c = 0; c < 4; c++) {
                            int row = row0g + mt * 16 + ((c >> 1) << 3);
                            int key = k0 + nt * 8 + t2 + (c & 1);
                            if (key > row) sacc[mt][nt][c] = -1e30f;
                        }
            }

            // online softmax: 4 row-states (mt x row-half)
            #pragma unroll
            for (int mt = 0; mt < 2; mt++) {
                float rm0 = -1e30f, rm1 = -1e30f;
                #pragma unroll
                for (int nt = 0; nt < 8; nt++) {
                    rm0 = fmaxf(rm0, fmaxf(sacc[mt][nt][0], sacc[mt][nt][1]));
                    rm1 = fmaxf(rm1, fmaxf(sacc[mt][nt][2], sacc[mt][nt][3]));
                }
                rm0 = fmaxf(rm0, __shfl_xor_sync(0xffffffffu, rm0, 1));
                rm0 = fmaxf(rm0, __shfl_xor_sync(0xffffffffu, rm0, 2));
                rm1 = fmaxf(rm1, __shfl_xor_sync(0xffffffffu, rm1, 1));
                rm1 = fmaxf(rm1, __shfl_xor_sync(0xffffffffu, rm1, 2));
                const float mn0 = fmaxf(mm[mt * 2 + 0], rm0);
                const float mn1 = fmaxf(mm[mt * 2 + 1], rm1);
                const float al0 = __expf(mm[mt * 2 + 0] - mn0);
                const float al1 = __expf(mm[mt * 2 + 1] - mn1);
                mm[mt * 2 + 0] = mn0; mm[mt * 2 + 1] = mn1;
                float rs0 = 0.f, rs1 = 0.f;
                #pragma unroll
                for (int nt = 0; nt < 8; nt++) {
                    float p0 = __expf(sacc[mt][nt][0] - mn0);
                    float p1 = __expf(sacc[mt][nt][1] - mn0);
                    float p2 = __expf(sacc[mt][nt][2] - mn1);
                    float p3 = __expf(sacc[mt][nt][3] - mn1);
                    sacc[mt][nt][0] = p0; sacc[mt][nt][1] = p1;
                    sacc[mt][nt][2] = p2; sacc[mt][nt][3] = p3;
                    rs0 += p0 + p1; rs1 += p2 + p3;
                }
                rs0 += __shfl_xor_sync(0xffffffffu, rs0, 1);
                rs0 += __shfl_xor_sync(0xffffffffu, rs0, 2);
                rs1 += __shfl_xor_sync(0xffffffffu, rs1, 1);
                rs1 += __shfl_xor_sync(0xffffffffu, rs1, 2);
                ll[mt * 2 + 0] = ll[mt * 2 + 0] * al0 + rs0;
                ll[mt * 2 + 1] = ll[mt * 2 + 1] * al1 + rs1;
                #pragma unroll
                for (int nt = 0; nt < 8; nt++) {
                    oacc[mt][nt][0] *= al0; oacc[mt][nt][1] *= al0;
                    oacc[mt][nt][2] *= al1; oacc[mt][nt][3] *= al1;
                }
            }

            // O += P V  (P split hi/lo; V split hi/lo; 3-term)
            #pragma unroll
            for (int ks2 = 0; ks2 < 4; ks2++) {
                uint32_t aP[2][4], aPl[2][4];
                #pragma unroll
                for (int mt = 0; mt < 2; mt++) {
                    #pragma unroll
                    for (int half = 0; half < 2; half++) {
                        const int nt = 2 * ks2 + half;
                        __nv_bfloat16 h00 = __float2bfloat16(sacc[mt][nt][0]);
                        __nv_bfloat16 h01 = __float2bfloat16(sacc[mt][nt][1]);
                        __nv_bfloat16 h10 = __float2bfloat16(sacc[mt][nt][2]);
                        __nv_bfloat16 h11 = __float2bfloat16(sacc[mt][nt][3]);
                        aP[mt][half * 2 + 0] = packbf(h00, h01);
                        aP[mt][half * 2 + 1] = packbf(h10, h11);
                        __nv_bfloat16 e00 = __float2bfloat16(sacc[mt][nt][0] - __bfloat162float(h00));
                        __nv_bfloat16 e01 = __float2bfloat16(sacc[mt][nt][1] - __bfloat162float(h01));
                        __nv_bfloat16 e10 = __float2bfloat16(sacc[mt][nt][2] - __bfloat162float(h10));
                        __nv_bfloat16 e11 = __float2bfloat16(sacc[mt][nt][3] - __bfloat162float(h11));
                        aPl[mt][half * 2 + 0] = packbf(e00, e01);
                        aPl[mt][half * 2 + 1] = packbf(e10, e11);
                    }
                }
                #pragma unroll
                for (int nt16 = 0; nt16 < 4; nt16++) {
                    const uint32_t voff =
                        swz128(ks2 * 16 + vb_row, nt16 * 2 + vb_ch);
                    uint32_t vH[4], vL[4];
                    ldsm4t(vH, bVH + voff);
                    ldsm4t(vL, bVL + voff);
                    #pragma unroll
                    for (int mt = 0; mt < 2; mt++) {
                        #pragma unroll
                        for (int i2 = 0; i2 < 2; i2++) {
                            float* c = oacc[mt][nt16 * 2 + i2];
                            mma16816(c, aP[mt], &vH[i2 * 2]);
                            mma16816(c, aP[mt], &vL[i2 * 2]);
                            mma16816(c, aPl[mt], &vH[i2 * 2]);
                        }
                    }
                }
            }
        }
        __syncthreads();
    }

    // Epilogue: normalize, write bf16 hi/lo into g_oh/g_ol [B,S,D]
    const int b = bh >> 4, h = bh & 15;
    #pragma unroll
    for (int mt = 0; mt < 2; mt++) {
        const float inv0 = 1.f / ll[mt * 2 + 0];
        const float inv1 = 1.f / ll[mt * 2 + 1];
        const int row0 = q0 + wid * 32 + mt * 16 + g;
        #pragma unroll
        for (int nt = 0; nt < 8; nt++) {
            const int col = h * HD + nt * 8 + t2;
            #pragma unroll
            for (int rh = 0; rh < 2; rh++) {
                const float inv = rh ? inv1 : inv0;
                const int row = row0 + rh * 8;
                float vx = oacc[mt][nt][rh * 2 + 0] * inv;
                float vy = oacc[mt][nt][rh * 2 + 1] * inv;
                __nv_bfloat16 hx = __float2bfloat16(vx);
                __nv_bfloat16 hy = __float2bfloat16(vy);
                __nv_bfloat16 lx = __float2bfloat16(vx - __bfloat162float(hx));
                __nv_bfloat16 ly = __float2bfloat16(vy - __bfloat162float(hy));
                size_t idx = (size_t)(b * Ss + row) * Dd + col;
                *(__nv_bfloat162*)&g_oh[idx] = __halves2bfloat162(hx, hy);
                *(__nv_bfloat162*)&g_ol[idx] = __halves2bfloat162(lx, ly);
            }
        }
    }
}

// ---------------------------------------------------------------------------
// Launch — only harness pointers cross the host/device boundary
// ---------------------------------------------------------------------------
extern "C" void kernel_launch(void* const* d_in, const int* in_sizes, int n_in,
                              void* d_out, int out_size)
{
    const float* x  = (const float*)d_in[0];
    const float* Wq = (const float*)d_in[1];
    const float* bq = (const float*)d_in[2];
    const float* Wk = (const float*)d_in[3];
    const float* bk = (const float*)d_in[4];
    const float* Wv = (const float*)d_in[5];
    const float* bv = (const float*)d_in[6];
    const float* Wp = (const float*)d_in[7];
    const float* bp = (const float*)d_in[8];
    float* out = (float*)d_out;

    cudaFuncSetAttribute(gemm_bf16x3<0>,
                         cudaFuncAttributeMaxDynamicSharedMemorySize, GEMM_SMEM);
    cudaFuncSetAttribute(gemm_bf16x3<1>,
                         cudaFuncAttributeMaxDynamicSharedMemorySize, GEMM_SMEM);
    cudaFuncSetAttribute(attn_mma,
                         cudaFuncAttributeMaxDynamicSharedMemorySize, ATT_SMEM);

    // Conversions
    const int n4 = Mtot * Dd / 4;
    k_conv_x<<<(n4 + 255) / 256, 256>>>(x, n4);
    k_conv_wqkv<<<dim3(16, 16, 3), 256>>>(Wq, Wk, Wv);
    k_conv_wp<<<dim3(16, 16), 256>>>(Wp);
    k_bias<<<12, 256>>>(bq, bk, bv);

    // QKV projection (q pre-scaled by 1/8; q/k/v hi/lo into [B,H,S,HD])
    gemm_bf16x3<1><<<dim3(24, 64), 128, GEMM_SMEM>>>(nullptr, nullptr);

    // Attention (mma.sync, split precision, 64-key stages, 2 CTAs/SM)
    attn_mma<<<dim3(16, 64), 128, ATT_SMEM>>>();

    // Output projection
    gemm_bf16x3<0><<<dim3(8, 64), 128, GEMM_SMEM>>>(bp, out);
}